// round 13
// baseline (speedup 1.0000x reference)
#include <cuda_runtime.h>
#include <cuda_fp16.h>
#include <cstdint>

// Problem constants
#define BATCH   2
#define SEQ     2048
#define HID     2048
#define NHEADS  16
#define HDIM    128
#define MROWS   (BATCH*SEQ)      // 4096
#define NQKV    (3*HID)          // 6144

// Scratch (device globals) — fp16; A-sides hi-only, B-sides hi/lo
__device__ __half g_qh[(size_t)BATCH*NHEADS*SEQ*HDIM];
__device__ __half g_kh[(size_t)BATCH*NHEADS*SEQ*HDIM], g_kl[(size_t)BATCH*NHEADS*SEQ*HDIM];
__device__ __half g_vh[(size_t)BATCH*NHEADS*SEQ*HDIM], g_vl[(size_t)BATCH*NHEADS*SEQ*HDIM];
__device__ __half g_hs_h[(size_t)MROWS*HID];
__device__ __half g_win_h[(size_t)NQKV*HID],  g_win_l[(size_t)NQKV*HID];
__device__ __half g_wout_h[(size_t)HID*HID],  g_wout_l[(size_t)HID*HID];
__device__ __half g_attn_h[(size_t)MROWS*HID];

__device__ __forceinline__ uint32_t smem_to_u32(const void* p) {
    uint32_t a;
    asm("{ .reg .u64 t; cvta.to.shared.u64 t, %1; cvt.u32.u64 %0, t; }"
        : "=r"(a) : "l"(p));
    return a;
}
__device__ __forceinline__ void ldsm_x4(uint32_t* r, uint32_t addr) {
    asm volatile("ldmatrix.sync.aligned.m8n8.x4.shared.b16 {%0,%1,%2,%3}, [%4];"
                 : "=r"(r[0]), "=r"(r[1]), "=r"(r[2]), "=r"(r[3]) : "r"(addr));
}
__device__ __forceinline__ void ldsm_x4t(uint32_t* r, uint32_t addr) {
    asm volatile("ldmatrix.sync.aligned.m8n8.x4.trans.shared.b16 {%0,%1,%2,%3}, [%4];"
                 : "=r"(r[0]), "=r"(r[1]), "=r"(r[2]), "=r"(r[3]) : "r"(addr));
}
__device__ __forceinline__ void mma_f16(float* d, const uint32_t* a,
                                        uint32_t b0, uint32_t b1) {
    asm volatile("mma.sync.aligned.m16n8k16.row.col.f32.f16.f16.f32 "
                 "{%0,%1,%2,%3}, {%4,%5,%6,%7}, {%8,%9}, {%0,%1,%2,%3};"
                 : "+f"(d[0]), "+f"(d[1]), "+f"(d[2]), "+f"(d[3])
                 : "r"(a[0]), "r"(a[1]), "r"(a[2]), "r"(a[3]), "r"(b0), "r"(b1));
}
__device__ __forceinline__ void cp_async16(uint32_t dst, const void* src) {
    asm volatile("cp.async.cg.shared.global [%0], [%1], 16;" :: "r"(dst), "l"(src));
}
#define CP_COMMIT()  asm volatile("cp.async.commit_group;")
#define CP_WAIT(n)   asm volatile("cp.async.wait_group %0;" :: "n"(n))

// fp32 pair -> fp16 hi pair (packed)
__device__ __forceinline__ uint32_t pack_h(float x0, float x1) {
    __half2 h = __float22half2_rn(make_float2(x0, x1));
    return *(uint32_t*)&h;
}
// fp32 pair -> fp16 hi + lo pairs
__device__ __forceinline__ uint32_t pack_hl(float x0, float x1, uint32_t& lo) {
    __half2 h = __float22half2_rn(make_float2(x0, x1));
    float2 hf = __half22float2(h);
    __half2 l = __float22half2_rn(make_float2(x0 - hf.x, x1 - hf.y));
    lo = *(uint32_t*)&l;
    return *(uint32_t*)&h;
}

// ---------------------------------------------------------------------------
// fp32 -> fp16 conversions
// ---------------------------------------------------------------------------
__global__ void cvt_h_kernel(const float* __restrict__ src,
                             __half* __restrict__ hi, int n4)
{
    for (int i = blockIdx.x * blockDim.x + threadIdx.x; i < n4;
         i += gridDim.x * blockDim.x) {
        float4 v = ((const float4*)src)[i];
        uint2 hp;
        hp.x = pack_h(v.x, v.y);
        hp.y = pack_h(v.z, v.w);
        ((uint2*)hi)[i] = hp;
    }
}
__global__ void cvt_hl_kernel(const float* __restrict__ src,
                              __half* __restrict__ hi,
                              __half* __restrict__ lo, int n4)
{
    for (int i = blockIdx.x * blockDim.x + threadIdx.x; i < n4;
         i += gridDim.x * blockDim.x) {
        float4 v = ((const float4*)src)[i];
        uint2 hp, lp;
        hp.x = pack_hl(v.x, v.y, lp.x);
        hp.y = pack_hl(v.z, v.w, lp.y);
        ((uint2*)hi)[i] = hp;
        ((uint2*)lo)[i] = lp;
    }
}

// ---------------------------------------------------------------------------
// HMMA GEMM (fp16 2-pass): out[m,n] = sum_k A[m,k]*W[n,k] + bias[n]
// A hi-only; B hi+lo. Passes: Ah*Bh + Ah*Bl.
// 512 threads (16 warps), block 128x256, warp 32x64, 2-stage cp.async.
// ---------------------------------------------------------------------------
#define ROWB 144
#define A_TILE_B (128*ROWB)       // 18432
#define B_TILE_B (256*ROWB)       // 36864
#define BT_HI A_TILE_B
#define BT_LO (A_TILE_B + B_TILE_B)
#define STAGE_B (A_TILE_B + 2*B_TILE_B)     // 92160
#define GEMM_SMEM (2*STAGE_B)               // 184320

template<int MODE, int KDIM>
__global__ __launch_bounds__(512, 1)
void gemm_mma_kernel(const __half* __restrict__ Ah,
                     const __half* __restrict__ Bh,
                     const __half* __restrict__ Bl,
                     const float* __restrict__ bias,
                     float* __restrict__ out)
{
    extern __shared__ char smem[];
    const uint32_t smb = smem_to_u32(smem);
    const int tid  = threadIdx.x;
    const int wid  = tid >> 5;
    const int lane = tid & 31;
    const int warp_m = wid & 3;
    const int warp_n = wid >> 2;
    const int row0 = blockIdx.y * 128;
    const int col0 = blockIdx.x * 256;
    constexpr int NCHUNK = KDIM / 64;

    const __half* srcA = Ah + (size_t)row0 * KDIM;
    const __half* srcB[2] = { Bh + (size_t)col0 * KDIM, Bl + (size_t)col0 * KDIM };

    auto issue = [&](int c, int st) {
        const int k0 = c * 64;
        const uint32_t sb = smb + st * STAGE_B;
        // A hi: 128 rows x 8 chunks = 1024 -> 2 iters
#pragma unroll
        for (int i = 0; i < 2; ++i) {
            int idx = i * 512 + tid;
            int row = idx >> 3, ch = idx & 7;
            cp_async16(sb + row * ROWB + ch * 16,
                       srcA + (size_t)row * KDIM + k0 + ch * 8);
        }
        // B hi/lo: 256 rows x 8 = 2048 each -> 4 iters each
#pragma unroll
        for (int t = 0; t < 2; ++t) {
            const __half* s = srcB[t];
            const uint32_t db = sb + BT_HI + t * B_TILE_B;
#pragma unroll
            for (int i = 0; i < 4; ++i) {
                int idx = i * 512 + tid;
                int row = idx >> 3, ch = idx & 7;
                cp_async16(db + row * ROWB + ch * 16,
                           s + (size_t)row * KDIM + k0 + ch * 8);
            }
        }
    };

    float acc[2][8][4];
#pragma unroll
    for (int i = 0; i < 2; i++)
#pragma unroll
        for (int j = 0; j < 8; j++)
#pragma unroll
            for (int q = 0; q < 4; q++) acc[i][j][q] = 0.f;

    const int rowA = (lane & 7) + ((lane >> 3) & 1) * 8;
    const int kA   = (lane >> 4) * 8;
    const int rowB = (lane & 7) + (lane >> 4) * 8;
    const int kB   = ((lane >> 3) & 1) * 8;

    issue(0, 0); CP_COMMIT();

    for (int c = 0; c < NCHUNK; ++c) {
        CP_WAIT(0);
        __syncthreads();
        if (c + 1 < NCHUNK) { issue(c + 1, (c + 1) & 1); CP_COMMIT(); }

        const uint32_t sb = smb + (c & 1) * STAGE_B;
        uint32_t aBase[2], bBase[4];
#pragma unroll
        for (int mf = 0; mf < 2; ++mf)
            aBase[mf] = sb + (warp_m * 32 + mf * 16 + rowA) * ROWB + kA * 2;
#pragma unroll
        for (int nf = 0; nf < 4; ++nf)
            bBase[nf] = sb + BT_HI + (warp_n * 64 + nf * 16 + rowB) * ROWB + kB * 2;

#pragma unroll
        for (int ks = 0; ks < 4; ++ks) {
            const int kb2 = ks * 32;
            uint32_t a_h[2][4];
#pragma unroll
            for (int mf = 0; mf < 2; ++mf)
                ldsm_x4(a_h[mf], aBase[mf] + kb2);
#pragma unroll
            for (int h = 0; h < 2; ++h) {
                uint32_t b_hi[2][4], b_lo[2][4];
#pragma unroll
                for (int j = 0; j < 2; ++j) {
                    ldsm_x4(b_hi[j], bBase[h * 2 + j] + kb2);
                    ldsm_x4(b_lo[j], bBase[h * 2 + j] + B_TILE_B + kb2);
                }
                // pass 1: Ah*Bh
#pragma unroll
                for (int mf = 0; mf < 2; ++mf)
#pragma unroll
                    for (int j = 0; j < 4; ++j) {
                        const uint32_t* bh = &b_hi[j >> 1][(j & 1) * 2];
                        mma_f16(acc[mf][h * 4 + j], a_h[mf], bh[0], bh[1]);
                    }
                // pass 2: Ah*Bl
#pragma unroll
                for (int mf = 0; mf < 2; ++mf)
#pragma unroll
                    for (int j = 0; j < 4; ++j) {
                        const uint32_t* bl = &b_lo[j >> 1][(j & 1) * 2];
                        mma_f16(acc[mf][h * 4 + j], a_h[mf], bl[0], bl[1]);
                    }
            }
        }
    }

    // Epilogue
#pragma unroll
    for (int mf = 0; mf < 2; ++mf) {
        const int rbase = row0 + warp_m * 32 + mf * 16 + (lane >> 2);
#pragma unroll
        for (int nf = 0; nf < 8; ++nf) {
            const int col = col0 + warp_n * 64 + nf * 8 + (lane & 3) * 2;
            float2 bv = *(const float2*)&bias[col];
#pragma unroll
            for (int half = 0; half < 2; ++half) {
                const int m = rbase + half * 8;
                float wx = acc[mf][nf][half * 2 + 0] + bv.x;
                float wy = acc[mf][nf][half * 2 + 1] + bv.y;
                if (MODE == 1) {
                    float2 w = {wx, wy};
                    *(float2*)(out + (size_t)m * HID + col) = w;
                } else {
                    const int which = col >> 11;             // 0=q 1=k 2=v
                    const int h2 = (col & 2047) >> 7;
                    const int d = col & 127;
                    const int b = m >> 11, sI = m & 2047;
                    size_t off = ((size_t)(b * NHEADS + h2) * SEQ + sI) * HDIM + d;
                    if (which == 0) {
                        *(uint32_t*)(g_qh + off) = pack_h(wx, wy);
                    } else {
                        __half* dh = (which == 1) ? g_kh : g_vh;
                        __half* dl = (which == 1) ? g_kl : g_vl;
                        uint32_t lo;
                        uint32_t hi = pack_hl(wx, wy, lo);
                        *(uint32_t*)(dh + off) = hi;
                        *(uint32_t*)(dl + off) = lo;
                    }
                }
            }
        }
    }
}

// ---------------------------------------------------------------------------
// Flash attention on HMMA (fp16 2-pass, causal).
// Q hi-only in registers; K hi/lo, V hi/lo in smem; 3-slot KV pipeline.
// Writes g_attn_h (fp16 hi) in [B,S,H].
// ---------------------------------------------------------------------------
#define FROWB 272
#define FKH 0
#define FKL (64*FROWB)
#define FVH (2*64*FROWB)
#define FVL (3*64*FROWB)
#define FSTAGE_B (4*64*FROWB)           // 69632
#define FLASH_SMEM (3*FSTAGE_B)         // 208896

__global__ __launch_bounds__(256, 1) void flash_mma_kernel()
{
    extern __shared__ char smem[];
    const uint32_t smb = smem_to_u32(smem);
    const int qt  = (int)gridDim.x - 1 - (int)blockIdx.x;   // heavy-first
    const int bh  = blockIdx.y;
    const int tid = threadIdx.x, wid = tid >> 5, lane = tid & 31;

    const size_t tb = (size_t)bh * SEQ * HDIM;
    const __half *Qh = g_qh + tb;
    const __half *Kh = g_kh + tb, *Kl = g_kl + tb;
    const __half *Vh = g_vh + tb, *Vl = g_vl + tb;

    const int ktmax = 2 * qt + 1;
    const uint32_t slot0 = smb, slot1 = smb + FSTAGE_B, slot2 = smb + 2 * FSTAGE_B;

    auto issue_kv = [&](int kt, uint32_t sb) {
        const __half* srcs[4] = {Kh, Kl, Vh, Vl};
#pragma unroll
        for (int t = 0; t < 4; ++t) {
#pragma unroll
            for (int i = 0; i < 4; ++i) {
                int idx = i * 256 + tid;
                int r = idx >> 4, ch = idx & 15;
                cp_async16(sb + t * (64 * FROWB) + r * FROWB + ch * 16,
                           srcs[t] + (size_t)(kt * 64 + r) * HDIM + ch * 8);
            }
        }
    };

    // Prologue: Q hi into slot2 (first half), recycled as KV slot after frag load
#pragma unroll
    for (int i = 0; i < 8; ++i) {
        int idx = i * 256 + tid;
        int r = idx >> 4, ch = idx & 15;
        cp_async16(slot2 + r * FROWB + ch * 16,
                   Qh + (size_t)(qt * 128 + r) * HDIM + ch * 8);
    }
    CP_COMMIT();
    issue_kv(0, slot0); CP_COMMIT();
    issue_kv(1, slot1); CP_COMMIT();

    CP_WAIT(2);
    __syncthreads();

    const uint32_t qaH = slot2 +
        (uint32_t)(wid * 16 + (lane & 7) + ((lane >> 3) & 1) * 8) * FROWB + (lane >> 4) * 16;
    uint32_t Qfh[8][4];
#pragma unroll
    for (int ks = 0; ks < 8; ++ks)
        ldsm_x4(Qfh[ks], qaH + ks * 32);

    const uint32_t koff = (uint32_t)((lane & 7) + (lane >> 4) * 8) * FROWB
                        + ((lane >> 3) & 1) * 16;
    const uint32_t voff = (uint32_t)((lane & 7) + ((lane >> 3) & 1) * 8) * FROWB
                        + (lane >> 4) * 16;

    float o[16][4];
#pragma unroll
    for (int i = 0; i < 16; i++)
#pragma unroll
        for (int j = 0; j < 4; j++) o[i][j] = 0.f;
    float m0 = -1e30f, m1 = -1e30f, l0 = 0.f, l1 = 0.f;
    const float scale = 0.08838834764831845f;

    const int wrow = qt * 128 + wid * 16;
    const int r0g = wrow + (lane >> 2);
    const int r1g = r0g + 8;

    for (int kt = 0; kt <= ktmax; ++kt) {
        CP_WAIT(1);
        __syncthreads();
        if (kt + 2 <= ktmax) {
            const uint32_t ws = ((kt + 2) % 3 == 0) ? slot0 :
                                ((kt + 2) % 3 == 1) ? slot1 : slot2;
            issue_kv(kt + 2, ws);
        }
        CP_COMMIT();

        const bool active = (kt * 64 <= wrow + 15);
        if (active) {
            const uint32_t sb = (kt % 3 == 0) ? slot0 : (kt % 3 == 1) ? slot1 : slot2;
            // ---- S = Q K^T (fp16 2-pass: Qh*Kh + Qh*Kl) ----
            float s[8][4];
#pragma unroll
            for (int i = 0; i < 8; i++)
#pragma unroll
                for (int j = 0; j < 4; j++) s[i][j] = 0.f;
#pragma unroll
            for (int ks = 0; ks < 8; ++ks) {
                uint32_t kh[4][4], kl[4][4];
#pragma unroll
                for (int c = 0; c < 4; ++c) {
                    ldsm_x4(kh[c], sb + FKH + koff + c * (16 * FROWB) + ks * 32);
                    ldsm_x4(kl[c], sb + FKL + koff + c * (16 * FROWB) + ks * 32);
                }
#pragma unroll
                for (int c = 0; c < 4; ++c) {
                    mma_f16(s[2*c],   Qfh[ks], kh[c][0], kh[c][1]);
                    mma_f16(s[2*c+1], Qfh[ks], kh[c][2], kh[c][3]);
                }
#pragma unroll
                for (int c = 0; c < 4; ++c) {
                    mma_f16(s[2*c],   Qfh[ks], kl[c][0], kl[c][1]);
                    mma_f16(s[2*c+1], Qfh[ks], kl[c][2], kl[c][3]);
                }
            }
            // ---- scale + causal mask ----
            const bool needmask = (kt * 64 + 63 > wrow);
#pragma unroll
            for (int nf = 0; nf < 8; ++nf) {
                const int kc = kt * 64 + nf * 8 + (lane & 3) * 2;
                s[nf][0] *= scale; s[nf][1] *= scale;
                s[nf][2] *= scale; s[nf][3] *= scale;
                if (needmask) {
                    if (kc     > r0g) s[nf][0] = -1e30f;
                    if (kc + 1 > r0g) s[nf][1] = -1e30f;
                    if (kc     > r1g) s[nf][2] = -1e30f;
                    if (kc + 1 > r1g) s[nf][3] = -1e30f;
                }
            }
            // ---- online softmax ----
            float mx0 = m0, mx1 = m1;
#pragma unroll
            for (int nf = 0; nf < 8; ++nf) {
                mx0 = fmaxf(mx0, fmaxf(s[nf][0], s[nf][1]));
                mx1 = fmaxf(mx1, fmaxf(s[nf][2], s[nf][3]));
            }
            mx0 = fmaxf(mx0, __shfl_xor_sync(0xffffffffu, mx0, 1));
            mx0 = fmaxf(mx0, __shfl_xor_sync(0xffffffffu, mx0, 2));
            mx1 = fmaxf(mx1, __shfl_xor_sync(0xffffffffu, mx1, 1));
            mx1 = fmaxf(mx1, __shfl_xor_sync(0xffffffffu, mx1, 2));
            const float a0 = __expf(m0 - mx0), a1 = __expf(m1 - mx1);
            m0 = mx0; m1 = mx1;
            float sum0 = 0.f, sum1 = 0.f;
#pragma unroll
            for (int nf = 0; nf < 8; ++nf) {
                s[nf][0] = __expf(s[nf][0] - mx0);
                s[nf][1] = __expf(s[nf][1] - mx0);
                s[nf][2] = __expf(s[nf][2] - mx1);
                s[nf][3] = __expf(s[nf][3] - mx1);
                sum0 += s[nf][0] + s[nf][1];
                sum1 += s[nf][2] + s[nf][3];
            }
            sum0 += __shfl_xor_sync(0xffffffffu, sum0, 1);
            sum0 += __shfl_xor_sync(0xffffffffu, sum0, 2);
            sum1 += __shfl_xor_sync(0xffffffffu, sum1, 1);
            sum1 += __shfl_xor_sync(0xffffffffu, sum1, 2);
            l0 = l0 * a0 + sum0;
            l1 = l1 * a1 + sum1;
#pragma unroll
            for (int nf = 0; nf < 16; ++nf) {
                o[nf][0] *= a0; o[nf][1] *= a0;
                o[nf][2] *= a1; o[nf][3] *= a1;
            }
            // ---- O += P V (fp16 2-pass: Ph*Vh + Ph*Vl) ----
#pragma unroll
            for (int ks2 = 0; ks2 < 4; ++ks2) {
                uint32_t ah[4];
                ah[0] = pack_h(s[2*ks2][0],   s[2*ks2][1]);
                ah[1] = pack_h(s[2*ks2][2],   s[2*ks2][3]);
                ah[2] = pack_h(s[2*ks2+1][0], s[2*ks2+1][1]);
                ah[3] = pack_h(s[2*ks2+1][2], s[2*ks2+1][3]);
#pragma unroll
                for (int dp = 0; dp < 4; ++dp) {
                    uint32_t v0h[4], v0l[4], v1h[4], v1l[4];
                    const uint32_t vb = sb + voff + ks2 * (16 * FROWB) + dp * 64;
                    ldsm_x4t(v0h, vb + FVH);
                    ldsm_x4t(v0l, vb + FVL);
                    ldsm_x4t(v1h, vb + FVH + 32);
                    ldsm_x4t(v1l, vb + FVL + 32);
                    float* o0 = o[4*dp + 0];
                    float* o1 = o[4*dp + 1];
                    float* o2 = o[4*dp + 2];
                    float* o3 = o[4*dp + 3];
                    mma_f16(o0, ah, v0h[0], v0h[1]);
                    mma_f16(o1, ah, v0h[2], v0h[3]);
                    mma_f16(o2, ah, v1h[0], v1h[1]);
                    mma_f16(o3, ah, v1h[2], v1h[3]);
                    mma_f16(o0, ah, v0l[0], v0l[1]);
                    mma_f16(o1, ah, v0l[2], v0l[3]);
                    mma_f16(o2, ah, v1l[0], v1l[1]);
                    mma_f16(o3, ah, v1l[2], v1l[3]);
                }
            }
        }
    }

    // ---- normalize + write fp16 hi to g_attn_h [B,S,H] ----
    const float inv0 = 1.f / l0, inv1 = 1.f / l1;
    const int b = bh >> 4, hd = bh & 15;
    const size_t ob0 = ((size_t)(b * SEQ + r0g)) * HID + hd * HDIM;
    const size_t ob1 = ob0 + (size_t)8 * HID;
#pragma unroll
    for (int nf = 0; nf < 16; ++nf) {
        const int col = nf * 8 + (lane & 3) * 2;
        *(uint32_t*)(g_attn_h + ob0 + col) = pack_h(o[nf][0] * inv0, o[nf][1] * inv0);
        *(uint32_t*)(g_attn_h + ob1 + col) = pack_h(o[nf][2] * inv1, o[nf][3] * inv1);
    }
}

// ---------------------------------------------------------------------------
extern "C" void kernel_launch(void* const* d_in, const int* in_sizes, int n_in,
                              void* d_out, int out_size)
{
    const float* hs    = (const float*)d_in[0];
    const float* W_in  = (const float*)d_in[1];
    const float* b_in  = (const float*)d_in[2];
    const float* W_out = (const float*)d_in[3];
    const float* b_out = (const float*)d_in[4];
    float* out = (float*)d_out;
    (void)in_sizes; (void)n_in; (void)out_size;

    cudaFuncSetAttribute(gemm_mma_kernel<0, HID>,
                         cudaFuncAttributeMaxDynamicSharedMemorySize, GEMM_SMEM);
    cudaFuncSetAttribute(gemm_mma_kernel<1, HID>,
                         cudaFuncAttributeMaxDynamicSharedMemorySize, GEMM_SMEM);
    cudaFuncSetAttribute(flash_mma_kernel,
                         cudaFuncAttributeMaxDynamicSharedMemorySize, FLASH_SMEM);

    __half *hs_h, *win_h, *win_l, *wout_h, *wout_l, *at_h;
    cudaGetSymbolAddress((void**)&hs_h,   g_hs_h);
    cudaGetSymbolAddress((void**)&win_h,  g_win_h);
    cudaGetSymbolAddress((void**)&win_l,  g_win_l);
    cudaGetSymbolAddress((void**)&wout_h, g_wout_h);
    cudaGetSymbolAddress((void**)&wout_l, g_wout_l);
    cudaGetSymbolAddress((void**)&at_h,   g_attn_h);

    // 0) fp32 -> fp16 conversions (A-sides hi-only, weights hi/lo)
    cvt_h_kernel <<<2048, 256>>>(hs,    hs_h,           MROWS * HID / 4);
    cvt_hl_kernel<<<2048, 256>>>(W_in,  win_h,  win_l,  NQKV * HID / 4);
    cvt_hl_kernel<<<2048, 256>>>(W_out, wout_h, wout_l, HID * HID / 4);

    // 1) QKV projection (fp16 2-pass) -> q hi / k hi,lo / v hi,lo head layout
    gemm_mma_kernel<0, HID><<<dim3(NQKV / 256, MROWS / 128), 512, GEMM_SMEM>>>(
        hs_h, win_h, win_l, b_in, nullptr);

    // 2) causal flash attention (fp16 2-pass) -> g_attn_h [B,S,H]
    flash_mma_kernel<<<dim3(SEQ / 128, BATCH * NHEADS), 256, FLASH_SMEM>>>();

    // 3) output projection (fp16 2-pass) -> d_out
    gemm_mma_kernel<1, HID><<<dim3(HID / 256, MROWS / 128), 512, GEMM_SMEM>>>(
        at_h, wout_h, wout_l, b_out, out);
}

// round 14
// speedup vs baseline: 1.2370x; 1.2370x over previous
#include <cuda_runtime.h>
#include <cuda_fp16.h>
#include <cstdint>

// Problem constants
#define BATCH   2
#define SEQ     2048
#define HID     2048
#define NHEADS  16
#define HDIM    128
#define MROWS   (BATCH*SEQ)      // 4096
#define NQKV    (3*HID)          // 6144

// Scratch — fp16; Q/attn hi-only, K hi/lo, V hi-only, W_in hi/lo, W_out hi-only
__device__ __half g_qh[(size_t)BATCH*NHEADS*SEQ*HDIM];
__device__ __half g_kh[(size_t)BATCH*NHEADS*SEQ*HDIM], g_kl[(size_t)BATCH*NHEADS*SEQ*HDIM];
__device__ __half g_vh[(size_t)BATCH*NHEADS*SEQ*HDIM];
__device__ __half g_hs_h[(size_t)MROWS*HID];
__device__ __half g_win_h[(size_t)NQKV*HID],  g_win_l[(size_t)NQKV*HID];
__device__ __half g_wout_h[(size_t)HID*HID];
__device__ __half g_attn_h[(size_t)MROWS*HID];

__device__ __forceinline__ uint32_t smem_to_u32(const void* p) {
    uint32_t a;
    asm("{ .reg .u64 t; cvta.to.shared.u64 t, %1; cvt.u32.u64 %0, t; }"
        : "=r"(a) : "l"(p));
    return a;
}
__device__ __forceinline__ void ldsm_x4(uint32_t* r, uint32_t addr) {
    asm volatile("ldmatrix.sync.aligned.m8n8.x4.shared.b16 {%0,%1,%2,%3}, [%4];"
                 : "=r"(r[0]), "=r"(r[1]), "=r"(r[2]), "=r"(r[3]) : "r"(addr));
}
__device__ __forceinline__ void ldsm_x4t(uint32_t* r, uint32_t addr) {
    asm volatile("ldmatrix.sync.aligned.m8n8.x4.trans.shared.b16 {%0,%1,%2,%3}, [%4];"
                 : "=r"(r[0]), "=r"(r[1]), "=r"(r[2]), "=r"(r[3]) : "r"(addr));
}
__device__ __forceinline__ void mma_f16(float* d, const uint32_t* a,
                                        uint32_t b0, uint32_t b1) {
    asm volatile("mma.sync.aligned.m16n8k16.row.col.f32.f16.f16.f32 "
                 "{%0,%1,%2,%3}, {%4,%5,%6,%7}, {%8,%9}, {%0,%1,%2,%3};"
                 : "+f"(d[0]), "+f"(d[1]), "+f"(d[2]), "+f"(d[3])
                 : "r"(a[0]), "r"(a[1]), "r"(a[2]), "r"(a[3]), "r"(b0), "r"(b1));
}
__device__ __forceinline__ void cp_async16(uint32_t dst, const void* src) {
    asm volatile("cp.async.cg.shared.global [%0], [%1], 16;" :: "r"(dst), "l"(src));
}
#define CP_COMMIT()  asm volatile("cp.async.commit_group;")
#define CP_WAIT(n)   asm volatile("cp.async.wait_group %0;" :: "n"(n))

__device__ __forceinline__ uint32_t pack_h(float x0, float x1) {
    __half2 h = __float22half2_rn(make_float2(x0, x1));
    return *(uint32_t*)&h;
}
__device__ __forceinline__ uint32_t pack_hl(float x0, float x1, uint32_t& lo) {
    __half2 h = __float22half2_rn(make_float2(x0, x1));
    float2 hf = __half22float2(h);
    __half2 l = __float22half2_rn(make_float2(x0 - hf.x, x1 - hf.y));
    lo = *(uint32_t*)&l;
    return *(uint32_t*)&h;
}

// ---------------------------------------------------------------------------
// fp32 -> fp16 conversions
// ---------------------------------------------------------------------------
__global__ void cvt_h_kernel(const float* __restrict__ src,
                             __half* __restrict__ hi, int n4)
{
    for (int i = blockIdx.x * blockDim.x + threadIdx.x; i < n4;
         i += gridDim.x * blockDim.x) {
        float4 v = ((const float4*)src)[i];
        uint2 hp;
        hp.x = pack_h(v.x, v.y);
        hp.y = pack_h(v.z, v.w);
        ((uint2*)hi)[i] = hp;
    }
}
__global__ void cvt_hl_kernel(const float* __restrict__ src,
                              __half* __restrict__ hi,
                              __half* __restrict__ lo, int n4)
{
    for (int i = blockIdx.x * blockDim.x + threadIdx.x; i < n4;
         i += gridDim.x * blockDim.x) {
        float4 v = ((const float4*)src)[i];
        uint2 hp, lp;
        hp.x = pack_hl(v.x, v.y, lp.x);
        hp.y = pack_hl(v.z, v.w, lp.y);
        ((uint2*)hi)[i] = hp;
        ((uint2*)lo)[i] = lp;
    }
}

// ---------------------------------------------------------------------------
// HMMA GEMM: out[m,n] = sum_k A[m,k]*W[n,k] + bias[n]
// Template: NTILE in {192,256}; PASSES in {1,2} (Ah*Bh [+ Ah*Bl]).
// 512 threads (16 warps), block 128 x NTILE, warp 32 x (NTILE/4).
// ---------------------------------------------------------------------------
#define ROWB 144

template<int MODE, int NTILE, int PASSES, int KDIM>
__global__ __launch_bounds__(512, 1)
void gemm_mma_kernel(const __half* __restrict__ Ah,
                     const __half* __restrict__ Bh,
                     const __half* __restrict__ Bl,
                     const float* __restrict__ bias,
                     float* __restrict__ out)
{
    constexpr int A_TILE = 128 * ROWB;
    constexpr int B_TILE = NTILE * ROWB;
    constexpr int STAGE  = A_TILE + PASSES * B_TILE;
    constexpr int G      = NTILE / 64;      // per-warp 16-row B groups
    constexpr int NF     = 2 * G;           // n8-fragments per warp

    extern __shared__ char smem[];
    const uint32_t smb = smem_to_u32(smem);
    const int tid  = threadIdx.x;
    const int wid  = tid >> 5;
    const int lane = tid & 31;
    const int warp_m = wid & 3;
    const int warp_n = wid >> 2;
    const int row0 = blockIdx.y * 128;
    const int col0 = blockIdx.x * NTILE;
    constexpr int NCHUNK = KDIM / 64;

    const __half* srcA = Ah + (size_t)row0 * KDIM;
    const __half* srcB[2] = { Bh + (size_t)col0 * KDIM,
                              (PASSES == 2) ? (Bl + (size_t)col0 * KDIM) : Bh };

    auto issue = [&](int c, int st) {
        const int k0 = c * 64;
        const uint32_t sb = smb + st * STAGE;
#pragma unroll
        for (int i = 0; i < 2; ++i) {              // A: 1024 xfers
            int idx = i * 512 + tid;
            int row = idx >> 3, ch = idx & 7;
            cp_async16(sb + row * ROWB + ch * 16,
                       srcA + (size_t)row * KDIM + k0 + ch * 8);
        }
#pragma unroll
        for (int t = 0; t < PASSES; ++t) {         // B: NTILE*8 xfers each
            const __half* s = srcB[t];
            const uint32_t db = sb + A_TILE + t * B_TILE;
#pragma unroll
            for (int i = 0; i < NTILE / 64; ++i) {
                int idx = i * 512 + tid;
                int row = idx >> 3, ch = idx & 7;
                cp_async16(db + row * ROWB + ch * 16,
                           s + (size_t)row * KDIM + k0 + ch * 8);
            }
        }
    };

    float acc[2][NF][4];
#pragma unroll
    for (int i = 0; i < 2; i++)
#pragma unroll
        for (int j = 0; j < NF; j++)
#pragma unroll
            for (int q = 0; q < 4; q++) acc[i][j][q] = 0.f;

    const int rowA = (lane & 7) + ((lane >> 3) & 1) * 8;
    const int kA   = (lane >> 4) * 8;
    const int rowB = (lane & 7) + (lane >> 4) * 8;
    const int kB   = ((lane >> 3) & 1) * 8;

    issue(0, 0); CP_COMMIT();

    for (int c = 0; c < NCHUNK; ++c) {
        CP_WAIT(0);
        __syncthreads();
        if (c + 1 < NCHUNK) { issue(c + 1, (c + 1) & 1); CP_COMMIT(); }

        const uint32_t sb = smb + (c & 1) * STAGE;
        uint32_t aBase[2], bBase[G];
#pragma unroll
        for (int mf = 0; mf < 2; ++mf)
            aBase[mf] = sb + (warp_m * 32 + mf * 16 + rowA) * ROWB + kA * 2;
#pragma unroll
        for (int g = 0; g < G; ++g)
            bBase[g] = sb + A_TILE + (warp_n * (NTILE / 4) + g * 16 + rowB) * ROWB + kB * 2;

#pragma unroll
        for (int ks = 0; ks < 4; ++ks) {
            const int kb2 = ks * 32;
            uint32_t a_h[2][4];
#pragma unroll
            for (int mf = 0; mf < 2; ++mf)
                ldsm_x4(a_h[mf], aBase[mf] + kb2);

            uint32_t b_hi[G][4], b_lo[G][4];
#pragma unroll
            for (int g = 0; g < G; ++g) {
                ldsm_x4(b_hi[g], bBase[g] + kb2);
                if (PASSES == 2) ldsm_x4(b_lo[g], bBase[g] + B_TILE + kb2);
            }
            // pass 1: Ah*Bh
#pragma unroll
            for (int mf = 0; mf < 2; ++mf)
#pragma unroll
                for (int nf = 0; nf < NF; ++nf) {
                    const uint32_t* bh = &b_hi[nf >> 1][(nf & 1) * 2];
                    mma_f16(acc[mf][nf], a_h[mf], bh[0], bh[1]);
                }
            // pass 2: Ah*Bl
            if (PASSES == 2) {
#pragma unroll
                for (int mf = 0; mf < 2; ++mf)
#pragma unroll
                    for (int nf = 0; nf < NF; ++nf) {
                        const uint32_t* bl = &b_lo[nf >> 1][(nf & 1) * 2];
                        mma_f16(acc[mf][nf], a_h[mf], bl[0], bl[1]);
                    }
            }
        }
    }

    // Epilogue
#pragma unroll
    for (int mf = 0; mf < 2; ++mf) {
        const int rbase = row0 + warp_m * 32 + mf * 16 + (lane >> 2);
#pragma unroll
        for (int nf = 0; nf < NF; ++nf) {
            const int col = col0 + warp_n * (NTILE / 4) + nf * 8 + (lane & 3) * 2;
            float2 bv = *(const float2*)&bias[col];
#pragma unroll
            for (int half = 0; half < 2; ++half) {
                const int m = rbase + half * 8;
                float wx = acc[mf][nf][half * 2 + 0] + bv.x;
                float wy = acc[mf][nf][half * 2 + 1] + bv.y;
                if (MODE == 1) {
                    float2 w = {wx, wy};
                    *(float2*)(out + (size_t)m * HID + col) = w;
                } else {
                    const int which = col >> 11;             // 0=q 1=k 2=v
                    const int h2 = (col & 2047) >> 7;
                    const int d = col & 127;
                    const int b = m >> 11, sI = m & 2047;
                    size_t off = ((size_t)(b * NHEADS + h2) * SEQ + sI) * HDIM + d;
                    if (which == 1) {                        // K: hi+lo
                        uint32_t lo;
                        uint32_t hi = pack_hl(wx, wy, lo);
                        *(uint32_t*)(g_kh + off) = hi;
                        *(uint32_t*)(g_kl + off) = lo;
                    } else {                                 // Q/V: hi only
                        __half* dh = (which == 0) ? g_qh : g_vh;
                        *(uint32_t*)(dh + off) = pack_h(wx, wy);
                    }
                }
            }
        }
    }
}

// ---------------------------------------------------------------------------
// Flash attention (fp16; QK 2-pass, PV 1-pass, causal).
// Q hi in registers; K hi/lo + V hi in smem; 3-slot KV pipeline.
// ---------------------------------------------------------------------------
#define FROWB 272
#define FKH 0
#define FKL (64*FROWB)
#define FVH (2*64*FROWB)
#define FSTAGE_B (3*64*FROWB)           // 52224
#define FLASH_SMEM (3*FSTAGE_B)         // 156672

__global__ __launch_bounds__(256, 1) void flash_mma_kernel()
{
    extern __shared__ char smem[];
    const uint32_t smb = smem_to_u32(smem);
    const int qt  = (int)gridDim.x - 1 - (int)blockIdx.x;   // heavy-first
    const int bh  = blockIdx.y;
    const int tid = threadIdx.x, wid = tid >> 5, lane = tid & 31;

    const size_t tb = (size_t)bh * SEQ * HDIM;
    const __half *Qh = g_qh + tb;
    const __half *Kh = g_kh + tb, *Kl = g_kl + tb;
    const __half *Vh = g_vh + tb;

    const int ktmax = 2 * qt + 1;
    const uint32_t slot0 = smb, slot1 = smb + FSTAGE_B, slot2 = smb + 2 * FSTAGE_B;

    auto issue_kv = [&](int kt, uint32_t sb) {
        const __half* srcs[3] = {Kh, Kl, Vh};
#pragma unroll
        for (int t = 0; t < 3; ++t) {
#pragma unroll
            for (int i = 0; i < 4; ++i) {
                int idx = i * 256 + tid;
                int r = idx >> 4, ch = idx & 15;
                cp_async16(sb + t * (64 * FROWB) + r * FROWB + ch * 16,
                           srcs[t] + (size_t)(kt * 64 + r) * HDIM + ch * 8);
            }
        }
    };

    // Prologue: Q hi into slot2 (recycled as KV slot after frag load)
#pragma unroll
    for (int i = 0; i < 8; ++i) {
        int idx = i * 256 + tid;
        int r = idx >> 4, ch = idx & 15;
        cp_async16(slot2 + r * FROWB + ch * 16,
                   Qh + (size_t)(qt * 128 + r) * HDIM + ch * 8);
    }
    CP_COMMIT();
    issue_kv(0, slot0); CP_COMMIT();
    issue_kv(1, slot1); CP_COMMIT();

    CP_WAIT(2);
    __syncthreads();

    const uint32_t qaH = slot2 +
        (uint32_t)(wid * 16 + (lane & 7) + ((lane >> 3) & 1) * 8) * FROWB + (lane >> 4) * 16;
    uint32_t Qfh[8][4];
#pragma unroll
    for (int ks = 0; ks < 8; ++ks)
        ldsm_x4(Qfh[ks], qaH + ks * 32);

    const uint32_t koff = (uint32_t)((lane & 7) + (lane >> 4) * 8) * FROWB
                        + ((lane >> 3) & 1) * 16;
    const uint32_t voff = (uint32_t)((lane & 7) + ((lane >> 3) & 1) * 8) * FROWB
                        + (lane >> 4) * 16;

    float o[16][4];
#pragma unroll
    for (int i = 0; i < 16; i++)
#pragma unroll
        for (int j = 0; j < 4; j++) o[i][j] = 0.f;
    float m0 = -1e30f, m1 = -1e30f, l0 = 0.f, l1 = 0.f;
    const float scale = 0.08838834764831845f;

    const int wrow = qt * 128 + wid * 16;
    const int r0g = wrow + (lane >> 2);
    const int r1g = r0g + 8;

    for (int kt = 0; kt <= ktmax; ++kt) {
        CP_WAIT(1);
        __syncthreads();
        if (kt + 2 <= ktmax) {
            const uint32_t ws = ((kt + 2) % 3 == 0) ? slot0 :
                                ((kt + 2) % 3 == 1) ? slot1 : slot2;
            issue_kv(kt + 2, ws);
        }
        CP_COMMIT();

        const bool active = (kt * 64 <= wrow + 15);
        if (active) {
            const uint32_t sb = (kt % 3 == 0) ? slot0 : (kt % 3 == 1) ? slot1 : slot2;
            // ---- S = Q K^T (2-pass: Qh*Kh + Qh*Kl) ----
            float s[8][4];
#pragma unroll
            for (int i = 0; i < 8; i++)
#pragma unroll
                for (int j = 0; j < 4; j++) s[i][j] = 0.f;
#pragma unroll
            for (int ks = 0; ks < 8; ++ks) {
                uint32_t kh[4][4], kl[4][4];
#pragma unroll
                for (int c = 0; c < 4; ++c) {
                    ldsm_x4(kh[c], sb + FKH + koff + c * (16 * FROWB) + ks * 32);
                    ldsm_x4(kl[c], sb + FKL + koff + c * (16 * FROWB) + ks * 32);
                }
#pragma unroll
                for (int c = 0; c < 4; ++c) {
                    mma_f16(s[2*c],   Qfh[ks], kh[c][0], kh[c][1]);
                    mma_f16(s[2*c+1], Qfh[ks], kh[c][2], kh[c][3]);
                }
#pragma unroll
                for (int c = 0; c < 4; ++c) {
                    mma_f16(s[2*c],   Qfh[ks], kl[c][0], kl[c][1]);
                    mma_f16(s[2*c+1], Qfh[ks], kl[c][2], kl[c][3]);
                }
            }
            // ---- scale + causal mask ----
            const bool needmask = (kt * 64 + 63 > wrow);
#pragma unroll
            for (int nf = 0; nf < 8; ++nf) {
                const int kc = kt * 64 + nf * 8 + (lane & 3) * 2;
                s[nf][0] *= scale; s[nf][1] *= scale;
                s[nf][2] *= scale; s[nf][3] *= scale;
                if (needmask) {
                    if (kc     > r0g) s[nf][0] = -1e30f;
                    if (kc + 1 > r0g) s[nf][1] = -1e30f;
                    if (kc     > r1g) s[nf][2] = -1e30f;
                    if (kc + 1 > r1g) s[nf][3] = -1e30f;
                }
            }
            // ---- online softmax ----
            float mx0 = m0, mx1 = m1;
#pragma unroll
            for (int nf = 0; nf < 8; ++nf) {
                mx0 = fmaxf(mx0, fmaxf(s[nf][0], s[nf][1]));
                mx1 = fmaxf(mx1, fmaxf(s[nf][2], s[nf][3]));
            }
            mx0 = fmaxf(mx0, __shfl_xor_sync(0xffffffffu, mx0, 1));
            mx0 = fmaxf(mx0, __shfl_xor_sync(0xffffffffu, mx0, 2));
            mx1 = fmaxf(mx1, __shfl_xor_sync(0xffffffffu, mx1, 1));
            mx1 = fmaxf(mx1, __shfl_xor_sync(0xffffffffu, mx1, 2));
            const float a0 = __expf(m0 - mx0), a1 = __expf(m1 - mx1);
            m0 = mx0; m1 = mx1;
            float sum0 = 0.f, sum1 = 0.f;
#pragma unroll
            for (int nf = 0; nf < 8; ++nf) {
                s[nf][0] = __expf(s[nf][0] - mx0);
                s[nf][1] = __expf(s[nf][1] - mx0);
                s[nf][2] = __expf(s[nf][2] - mx1);
                s[nf][3] = __expf(s[nf][3] - mx1);
                sum0 += s[nf][0] + s[nf][1];
                sum1 += s[nf][2] + s[nf][3];
            }
            sum0 += __shfl_xor_sync(0xffffffffu, sum0, 1);
            sum0 += __shfl_xor_sync(0xffffffffu, sum0, 2);
            sum1 += __shfl_xor_sync(0xffffffffu, sum1, 1);
            sum1 += __shfl_xor_sync(0xffffffffu, sum1, 2);
            l0 = l0 * a0 + sum0;
            l1 = l1 * a1 + sum1;
#pragma unroll
            for (int nf = 0; nf < 16; ++nf) {
                o[nf][0] *= a0; o[nf][1] *= a0;
                o[nf][2] *= a1; o[nf][3] *= a1;
            }
            // ---- O += P V (1-pass: Ph*Vh) ----
#pragma unroll
            for (int ks2 = 0; ks2 < 4; ++ks2) {
                uint32_t ah[4];
                ah[0] = pack_h(s[2*ks2][0],   s[2*ks2][1]);
                ah[1] = pack_h(s[2*ks2][2],   s[2*ks2][3]);
                ah[2] = pack_h(s[2*ks2+1][0], s[2*ks2+1][1]);
                ah[3] = pack_h(s[2*ks2+1][2], s[2*ks2+1][3]);
#pragma unroll
                for (int dp = 0; dp < 4; ++dp) {
                    uint32_t v0h[4], v1h[4];
                    const uint32_t vb = sb + voff + ks2 * (16 * FROWB) + dp * 64;
                    ldsm_x4t(v0h, vb + FVH);
                    ldsm_x4t(v1h, vb + FVH + 32);
                    mma_f16(o[4*dp + 0], ah, v0h[0], v0h[1]);
                    mma_f16(o[4*dp + 1], ah, v0h[2], v0h[3]);
                    mma_f16(o[4*dp + 2], ah, v1h[0], v1h[1]);
                    mma_f16(o[4*dp + 3], ah, v1h[2], v1h[3]);
                }
            }
        }
    }

    // ---- normalize + write fp16 hi to g_attn_h [B,S,H] ----
    const float inv0 = 1.f / l0, inv1 = 1.f / l1;
    const int b = bh >> 4, hd = bh & 15;
    const size_t ob0 = ((size_t)(b * SEQ + r0g)) * HID + hd * HDIM;
    const size_t ob1 = ob0 + (size_t)8 * HID;
#pragma unroll
    for (int nf = 0; nf < 16; ++nf) {
        const int col = nf * 8 + (lane & 3) * 2;
        *(uint32_t*)(g_attn_h + ob0 + col) = pack_h(o[nf][0] * inv0, o[nf][1] * inv0);
        *(uint32_t*)(g_attn_h + ob1 + col) = pack_h(o[nf][2] * inv1, o[nf][3] * inv1);
    }
}

// ---------------------------------------------------------------------------
extern "C" void kernel_launch(void* const* d_in, const int* in_sizes, int n_in,
                              void* d_out, int out_size)
{
    const float* hs    = (const float*)d_in[0];
    const float* W_in  = (const float*)d_in[1];
    const float* b_in  = (const float*)d_in[2];
    const float* W_out = (const float*)d_in[3];
    const float* b_out = (const float*)d_in[4];
    float* out = (float*)d_out;
    (void)in_sizes; (void)n_in; (void)out_size;

    // smem sizes
    constexpr int SM_QKV = 2 * (128 * ROWB + 2 * 192 * ROWB);   // 147456
    constexpr int SM_OUT = 2 * (128 * ROWB + 1 * 256 * ROWB);   // 110592

    cudaFuncSetAttribute((const void*)gemm_mma_kernel<0, 192, 2, HID>,
                         cudaFuncAttributeMaxDynamicSharedMemorySize, SM_QKV);
    cudaFuncSetAttribute((const void*)gemm_mma_kernel<1, 256, 1, HID>,
                         cudaFuncAttributeMaxDynamicSharedMemorySize, SM_OUT);
    cudaFuncSetAttribute(flash_mma_kernel,
                         cudaFuncAttributeMaxDynamicSharedMemorySize, FLASH_SMEM);

    __half *hs_h, *win_h, *win_l, *wout_h, *at_h;
    cudaGetSymbolAddress((void**)&hs_h,   g_hs_h);
    cudaGetSymbolAddress((void**)&win_h,  g_win_h);
    cudaGetSymbolAddress((void**)&win_l,  g_win_l);
    cudaGetSymbolAddress((void**)&wout_h, g_wout_h);
    cudaGetSymbolAddress((void**)&at_h,   g_attn_h);

    // 0) fp32 -> fp16 conversions
    cvt_h_kernel <<<2048, 256>>>(hs,    hs_h,          MROWS * HID / 4);
    cvt_hl_kernel<<<2048, 256>>>(W_in,  win_h, win_l,  NQKV * HID / 4);
    cvt_h_kernel <<<2048, 256>>>(W_out, wout_h,        HID * HID / 4);

    // 1) QKV projection (2-pass, N-tile 192 -> 1024 blocks, 98.8% wave eff)
    gemm_mma_kernel<0, 192, 2, HID>
        <<<dim3(NQKV / 192, MROWS / 128), 512, SM_QKV>>>(
        hs_h, win_h, win_l, b_in, nullptr);

    // 2) causal flash attention (QK 2-pass, PV 1-pass) -> g_attn_h
    flash_mma_kernel<<<dim3(SEQ / 128, BATCH * NHEADS), 256, FLASH_SMEM>>>();

    // 3) output projection (1-pass) -> d_out
    gemm_mma_kernel<1, 256, 1, HID>
        <<<dim3(HID / 256, MROWS / 128), 512, SM_OUT>>>(
        at_h, wout_h, nullptr, b_out, out);
}

// round 15
// speedup vs baseline: 1.2397x; 1.0022x over previous
#include <cuda_runtime.h>
#include <cuda_fp16.h>
#include <cstdint>

// Problem constants
#define BATCH   2
#define SEQ     2048
#define HID     2048
#define NHEADS  16
#define HDIM    128
#define MROWS   (BATCH*SEQ)      // 4096
#define NQKV    (3*HID)          // 6144

// Scratch — fp16; Q/attn hi-only, K hi/lo, V hi-only, W_in hi/lo, W_out hi-only
__device__ __half g_qh[(size_t)BATCH*NHEADS*SEQ*HDIM];
__device__ __half g_kh[(size_t)BATCH*NHEADS*SEQ*HDIM], g_kl[(size_t)BATCH*NHEADS*SEQ*HDIM];
__device__ __half g_vh[(size_t)BATCH*NHEADS*SEQ*HDIM];
__device__ __half g_hs_h[(size_t)MROWS*HID];
__device__ __half g_win_h[(size_t)NQKV*HID],  g_win_l[(size_t)NQKV*HID];
__device__ __half g_wout_h[(size_t)HID*HID];
__device__ __half g_attn_h[(size_t)MROWS*HID];

__device__ __forceinline__ uint32_t smem_to_u32(const void* p) {
    uint32_t a;
    asm("{ .reg .u64 t; cvta.to.shared.u64 t, %1; cvt.u32.u64 %0, t; }"
        : "=r"(a) : "l"(p));
    return a;
}
__device__ __forceinline__ void ldsm_x4(uint32_t* r, uint32_t addr) {
    asm volatile("ldmatrix.sync.aligned.m8n8.x4.shared.b16 {%0,%1,%2,%3}, [%4];"
                 : "=r"(r[0]), "=r"(r[1]), "=r"(r[2]), "=r"(r[3]) : "r"(addr));
}
__device__ __forceinline__ void ldsm_x4t(uint32_t* r, uint32_t addr) {
    asm volatile("ldmatrix.sync.aligned.m8n8.x4.trans.shared.b16 {%0,%1,%2,%3}, [%4];"
                 : "=r"(r[0]), "=r"(r[1]), "=r"(r[2]), "=r"(r[3]) : "r"(addr));
}
__device__ __forceinline__ void mma_f16(float* d, const uint32_t* a,
                                        uint32_t b0, uint32_t b1) {
    asm volatile("mma.sync.aligned.m16n8k16.row.col.f32.f16.f16.f32 "
                 "{%0,%1,%2,%3}, {%4,%5,%6,%7}, {%8,%9}, {%0,%1,%2,%3};"
                 : "+f"(d[0]), "+f"(d[1]), "+f"(d[2]), "+f"(d[3])
                 : "r"(a[0]), "r"(a[1]), "r"(a[2]), "r"(a[3]), "r"(b0), "r"(b1));
}
__device__ __forceinline__ void cp_async16(uint32_t dst, const void* src) {
    asm volatile("cp.async.cg.shared.global [%0], [%1], 16;" :: "r"(dst), "l"(src));
}
#define CP_COMMIT()  asm volatile("cp.async.commit_group;")
#define CP_WAIT(n)   asm volatile("cp.async.wait_group %0;" :: "n"(n))

__device__ __forceinline__ uint32_t pack_h(float x0, float x1) {
    __half2 h = __float22half2_rn(make_float2(x0, x1));
    return *(uint32_t*)&h;
}
__device__ __forceinline__ uint32_t pack_hl(float x0, float x1, uint32_t& lo) {
    __half2 h = __float22half2_rn(make_float2(x0, x1));
    float2 hf = __half22float2(h);
    __half2 l = __float22half2_rn(make_float2(x0 - hf.x, x1 - hf.y));
    lo = *(uint32_t*)&l;
    return *(uint32_t*)&h;
}

// ---------------------------------------------------------------------------
// fp32 -> fp16 conversions
// ---------------------------------------------------------------------------
__global__ void cvt_h_kernel(const float* __restrict__ src,
                             __half* __restrict__ hi, int n4)
{
    for (int i = blockIdx.x * blockDim.x + threadIdx.x; i < n4;
         i += gridDim.x * blockDim.x) {
        float4 v = ((const float4*)src)[i];
        uint2 hp;
        hp.x = pack_h(v.x, v.y);
        hp.y = pack_h(v.z, v.w);
        ((uint2*)hi)[i] = hp;
    }
}
__global__ void cvt_hl_kernel(const float* __restrict__ src,
                              __half* __restrict__ hi,
                              __half* __restrict__ lo, int n4)
{
    for (int i = blockIdx.x * blockDim.x + threadIdx.x; i < n4;
         i += gridDim.x * blockDim.x) {
        float4 v = ((const float4*)src)[i];
        uint2 hp, lp;
        hp.x = pack_hl(v.x, v.y, lp.x);
        hp.y = pack_hl(v.z, v.w, lp.y);
        ((uint2*)hi)[i] = hp;
        ((uint2*)lo)[i] = lp;
    }
}

// ---------------------------------------------------------------------------
// HMMA GEMM: out[m,n] = sum_k A[m,k]*W[n,k] + bias[n]
// Template: NTILE in {192,256}; PASSES in {1,2} (Ah*Bh [+ Ah*Bl]).
// 512 threads (16 warps), block 128 x NTILE, warp 32 x (NTILE/4).
// ---------------------------------------------------------------------------
#define ROWB 144

template<int MODE, int NTILE, int PASSES, int KDIM>
__global__ __launch_bounds__(512, 1)
void gemm_mma_kernel(const __half* __restrict__ Ah,
                     const __half* __restrict__ Bh,
                     const __half* __restrict__ Bl,
                     const float* __restrict__ bias,
                     float* __restrict__ out)
{
    constexpr int A_TILE = 128 * ROWB;
    constexpr int B_TILE = NTILE * ROWB;
    constexpr int STAGE  = A_TILE + PASSES * B_TILE;
    constexpr int G      = NTILE / 64;      // per-warp 16-row B groups
    constexpr int NF     = 2 * G;           // n8-fragments per warp

    extern __shared__ char smem[];
    const uint32_t smb = smem_to_u32(smem);
    const int tid  = threadIdx.x;
    const int wid  = tid >> 5;
    const int lane = tid & 31;
    const int warp_m = wid & 3;
    const int warp_n = wid >> 2;
    const int row0 = blockIdx.y * 128;
    const int col0 = blockIdx.x * NTILE;
    constexpr int NCHUNK = KDIM / 64;

    const __half* srcA = Ah + (size_t)row0 * KDIM;
    const __half* srcB[2] = { Bh + (size_t)col0 * KDIM,
                              (PASSES == 2) ? (Bl + (size_t)col0 * KDIM) : Bh };

    auto issue = [&](int c, int st) {
        const int k0 = c * 64;
        const uint32_t sb = smb + st * STAGE;
#pragma unroll
        for (int i = 0; i < 2; ++i) {              // A: 1024 xfers
            int idx = i * 512 + tid;
            int row = idx >> 3, ch = idx & 7;
            cp_async16(sb + row * ROWB + ch * 16,
                       srcA + (size_t)row * KDIM + k0 + ch * 8);
        }
#pragma unroll
        for (int t = 0; t < PASSES; ++t) {         // B: NTILE*8 xfers each
            const __half* s = srcB[t];
            const uint32_t db = sb + A_TILE + t * B_TILE;
#pragma unroll
            for (int i = 0; i < NTILE / 64; ++i) {
                int idx = i * 512 + tid;
                int row = idx >> 3, ch = idx & 7;
                cp_async16(db + row * ROWB + ch * 16,
                           s + (size_t)row * KDIM + k0 + ch * 8);
            }
        }
    };

    float acc[2][NF][4];
#pragma unroll
    for (int i = 0; i < 2; i++)
#pragma unroll
        for (int j = 0; j < NF; j++)
#pragma unroll
            for (int q = 0; q < 4; q++) acc[i][j][q] = 0.f;

    const int rowA = (lane & 7) + ((lane >> 3) & 1) * 8;
    const int kA   = (lane >> 4) * 8;
    const int rowB = (lane & 7) + (lane >> 4) * 8;
    const int kB   = ((lane >> 3) & 1) * 8;

    issue(0, 0); CP_COMMIT();

    for (int c = 0; c < NCHUNK; ++c) {
        CP_WAIT(0);
        __syncthreads();
        if (c + 1 < NCHUNK) { issue(c + 1, (c + 1) & 1); CP_COMMIT(); }

        const uint32_t sb = smb + (c & 1) * STAGE;
        uint32_t aBase[2], bBase[G];
#pragma unroll
        for (int mf = 0; mf < 2; ++mf)
            aBase[mf] = sb + (warp_m * 32 + mf * 16 + rowA) * ROWB + kA * 2;
#pragma unroll
        for (int g = 0; g < G; ++g)
            bBase[g] = sb + A_TILE + (warp_n * (NTILE / 4) + g * 16 + rowB) * ROWB + kB * 2;

#pragma unroll
        for (int ks = 0; ks < 4; ++ks) {
            const int kb2 = ks * 32;
            uint32_t a_h[2][4];
#pragma unroll
            for (int mf = 0; mf < 2; ++mf)
                ldsm_x4(a_h[mf], aBase[mf] + kb2);

            uint32_t b_hi[G][4], b_lo[G][4];
#pragma unroll
            for (int g = 0; g < G; ++g) {
                ldsm_x4(b_hi[g], bBase[g] + kb2);
                if (PASSES == 2) ldsm_x4(b_lo[g], bBase[g] + B_TILE + kb2);
            }
            // pass 1: Ah*Bh
#pragma unroll
            for (int mf = 0; mf < 2; ++mf)
#pragma unroll
                for (int nf = 0; nf < NF; ++nf) {
                    const uint32_t* bh = &b_hi[nf >> 1][(nf & 1) * 2];
                    mma_f16(acc[mf][nf], a_h[mf], bh[0], bh[1]);
                }
            // pass 2: Ah*Bl
            if (PASSES == 2) {
#pragma unroll
                for (int mf = 0; mf < 2; ++mf)
#pragma unroll
                    for (int nf = 0; nf < NF; ++nf) {
                        const uint32_t* bl = &b_lo[nf >> 1][(nf & 1) * 2];
                        mma_f16(acc[mf][nf], a_h[mf], bl[0], bl[1]);
                    }
            }
        }
    }

    // Epilogue
#pragma unroll
    for (int mf = 0; mf < 2; ++mf) {
        const int rbase = row0 + warp_m * 32 + mf * 16 + (lane >> 2);
#pragma unroll
        for (int nf = 0; nf < NF; ++nf) {
            const int col = col0 + warp_n * (NTILE / 4) + nf * 8 + (lane & 3) * 2;
            float2 bv = *(const float2*)&bias[col];
#pragma unroll
            for (int half = 0; half < 2; ++half) {
                const int m = rbase + half * 8;
                float wx = acc[mf][nf][half * 2 + 0] + bv.x;
                float wy = acc[mf][nf][half * 2 + 1] + bv.y;
                if (MODE == 1) {
                    float2 w = {wx, wy};
                    *(float2*)(out + (size_t)m * HID + col) = w;
                } else {
                    const int which = col >> 11;             // 0=q 1=k 2=v
                    const int h2 = (col & 2047) >> 7;
                    const int d = col & 127;
                    const int b = m >> 11, sI = m & 2047;
                    size_t off = ((size_t)(b * NHEADS + h2) * SEQ + sI) * HDIM + d;
                    if (which == 1) {                        // K: hi+lo
                        uint32_t lo;
                        uint32_t hi = pack_hl(wx, wy, lo);
                        *(uint32_t*)(g_kh + off) = hi;
                        *(uint32_t*)(g_kl + off) = lo;
                    } else {                                 // Q/V: hi only
                        __half* dh = (which == 0) ? g_qh : g_vh;
                        *(uint32_t*)(dh + off) = pack_h(wx, wy);
                    }
                }
            }
        }
    }
}

// ---------------------------------------------------------------------------
// Flash attention (fp16; QK 2-pass, PV 1-pass, causal).
// Q hi in registers; K hi/lo + V hi in smem; 3-slot KV pipeline.
// ---------------------------------------------------------------------------
#define FROWB 272
#define FKH 0
#define FKL (64*FROWB)
#define FVH (2*64*FROWB)
#define FSTAGE_B (3*64*FROWB)           // 52224
#define FLASH_SMEM (3*FSTAGE_B)         // 156672

__global__ __launch_bounds__(256, 1) void flash_mma_kernel()
{
    extern __shared__ char smem[];
    const uint32_t smb = smem_to_u32(smem);
    const int qt  = (int)gridDim.x - 1 - (int)blockIdx.x;   // heavy-first
    const int bh  = blockIdx.y;
    const int tid = threadIdx.x, wid = tid >> 5, lane = tid & 31;

    const size_t tb = (size_t)bh * SEQ * HDIM;
    const __half *Qh = g_qh + tb;
    const __half *Kh = g_kh + tb, *Kl = g_kl + tb;
    const __half *Vh = g_vh + tb;

    const int ktmax = 2 * qt + 1;
    const uint32_t slot0 = smb, slot1 = smb + FSTAGE_B, slot2 = smb + 2 * FSTAGE_B;

    auto issue_kv = [&](int kt, uint32_t sb) {
        const __half* srcs[3] = {Kh, Kl, Vh};
#pragma unroll
        for (int t = 0; t < 3; ++t) {
#pragma unroll
            for (int i = 0; i < 4; ++i) {
                int idx = i * 256 + tid;
                int r = idx >> 4, ch = idx & 15;
                cp_async16(sb + t * (64 * FROWB) + r * FROWB + ch * 16,
                           srcs[t] + (size_t)(kt * 64 + r) * HDIM + ch * 8);
            }
        }
    };

    // Prologue: Q hi into slot2 (recycled as KV slot after frag load)
#pragma unroll
    for (int i = 0; i < 8; ++i) {
        int idx = i * 256 + tid;
        int r = idx >> 4, ch = idx & 15;
        cp_async16(slot2 + r * FROWB + ch * 16,
                   Qh + (size_t)(qt * 128 + r) * HDIM + ch * 8);
    }
    CP_COMMIT();
    issue_kv(0, slot0); CP_COMMIT();
    issue_kv(1, slot1); CP_COMMIT();

    CP_WAIT(2);
    __syncthreads();

    const uint32_t qaH = slot2 +
        (uint32_t)(wid * 16 + (lane & 7) + ((lane >> 3) & 1) * 8) * FROWB + (lane >> 4) * 16;
    uint32_t Qfh[8][4];
#pragma unroll
    for (int ks = 0; ks < 8; ++ks)
        ldsm_x4(Qfh[ks], qaH + ks * 32);

    const uint32_t koff = (uint32_t)((lane & 7) + (lane >> 4) * 8) * FROWB
                        + ((lane >> 3) & 1) * 16;
    const uint32_t voff = (uint32_t)((lane & 7) + ((lane >> 3) & 1) * 8) * FROWB
                        + (lane >> 4) * 16;

    float o[16][4];
#pragma unroll
    for (int i = 0; i < 16; i++)
#pragma unroll
        for (int j = 0; j < 4; j++) o[i][j] = 0.f;
    float m0 = -1e30f, m1 = -1e30f, l0 = 0.f, l1 = 0.f;
    const float scale = 0.08838834764831845f;

    const int wrow = qt * 128 + wid * 16;
    const int r0g = wrow + (lane >> 2);
    const int r1g = r0g + 8;

    for (int kt = 0; kt <= ktmax; ++kt) {
        CP_WAIT(1);
        __syncthreads();
        if (kt + 2 <= ktmax) {
            const uint32_t ws = ((kt + 2) % 3 == 0) ? slot0 :
                                ((kt + 2) % 3 == 1) ? slot1 : slot2;
            issue_kv(kt + 2, ws);
        }
        CP_COMMIT();

        const bool active = (kt * 64 <= wrow + 15);
        if (active) {
            const uint32_t sb = (kt % 3 == 0) ? slot0 : (kt % 3 == 1) ? slot1 : slot2;
            // ---- S = Q K^T (2-pass: Qh*Kh + Qh*Kl) ----
            float s[8][4];
#pragma unroll
            for (int i = 0; i < 8; i++)
#pragma unroll
                for (int j = 0; j < 4; j++) s[i][j] = 0.f;
#pragma unroll
            for (int ks = 0; ks < 8; ++ks) {
                uint32_t kh[4][4], kl[4][4];
#pragma unroll
                for (int c = 0; c < 4; ++c) {
                    ldsm_x4(kh[c], sb + FKH + koff + c * (16 * FROWB) + ks * 32);
                    ldsm_x4(kl[c], sb + FKL + koff + c * (16 * FROWB) + ks * 32);
                }
#pragma unroll
                for (int c = 0; c < 4; ++c) {
                    mma_f16(s[2*c],   Qfh[ks], kh[c][0], kh[c][1]);
                    mma_f16(s[2*c+1], Qfh[ks], kh[c][2], kh[c][3]);
                }
#pragma unroll
                for (int c = 0; c < 4; ++c) {
                    mma_f16(s[2*c],   Qfh[ks], kl[c][0], kl[c][1]);
                    mma_f16(s[2*c+1], Qfh[ks], kl[c][2], kl[c][3]);
                }
            }
            // ---- scale + causal mask ----
            const bool needmask = (kt * 64 + 63 > wrow);
#pragma unroll
            for (int nf = 0; nf < 8; ++nf) {
                const int kc = kt * 64 + nf * 8 + (lane & 3) * 2;
                s[nf][0] *= scale; s[nf][1] *= scale;
                s[nf][2] *= scale; s[nf][3] *= scale;
                if (needmask) {
                    if (kc     > r0g) s[nf][0] = -1e30f;
                    if (kc + 1 > r0g) s[nf][1] = -1e30f;
                    if (kc     > r1g) s[nf][2] = -1e30f;
                    if (kc + 1 > r1g) s[nf][3] = -1e30f;
                }
            }
            // ---- online softmax ----
            float mx0 = m0, mx1 = m1;
#pragma unroll
            for (int nf = 0; nf < 8; ++nf) {
                mx0 = fmaxf(mx0, fmaxf(s[nf][0], s[nf][1]));
                mx1 = fmaxf(mx1, fmaxf(s[nf][2], s[nf][3]));
            }
            mx0 = fmaxf(mx0, __shfl_xor_sync(0xffffffffu, mx0, 1));
            mx0 = fmaxf(mx0, __shfl_xor_sync(0xffffffffu, mx0, 2));
            mx1 = fmaxf(mx1, __shfl_xor_sync(0xffffffffu, mx1, 1));
            mx1 = fmaxf(mx1, __shfl_xor_sync(0xffffffffu, mx1, 2));
            const float a0 = __expf(m0 - mx0), a1 = __expf(m1 - mx1);
            m0 = mx0; m1 = mx1;
            float sum0 = 0.f, sum1 = 0.f;
#pragma unroll
            for (int nf = 0; nf < 8; ++nf) {
                s[nf][0] = __expf(s[nf][0] - mx0);
                s[nf][1] = __expf(s[nf][1] - mx0);
                s[nf][2] = __expf(s[nf][2] - mx1);
                s[nf][3] = __expf(s[nf][3] - mx1);
                sum0 += s[nf][0] + s[nf][1];
                sum1 += s[nf][2] + s[nf][3];
            }
            sum0 += __shfl_xor_sync(0xffffffffu, sum0, 1);
            sum0 += __shfl_xor_sync(0xffffffffu, sum0, 2);
            sum1 += __shfl_xor_sync(0xffffffffu, sum1, 1);
            sum1 += __shfl_xor_sync(0xffffffffu, sum1, 2);
            l0 = l0 * a0 + sum0;
            l1 = l1 * a1 + sum1;
#pragma unroll
            for (int nf = 0; nf < 16; ++nf) {
                o[nf][0] *= a0; o[nf][1] *= a0;
                o[nf][2] *= a1; o[nf][3] *= a1;
            }
            // ---- O += P V (1-pass: Ph*Vh) ----
#pragma unroll
            for (int ks2 = 0; ks2 < 4; ++ks2) {
                uint32_t ah[4];
                ah[0] = pack_h(s[2*ks2][0],   s[2*ks2][1]);
                ah[1] = pack_h(s[2*ks2][2],   s[2*ks2][3]);
                ah[2] = pack_h(s[2*ks2+1][0], s[2*ks2+1][1]);
                ah[3] = pack_h(s[2*ks2+1][2], s[2*ks2+1][3]);
#pragma unroll
                for (int dp = 0; dp < 4; ++dp) {
                    uint32_t v0h[4], v1h[4];
                    const uint32_t vb = sb + voff + ks2 * (16 * FROWB) + dp * 64;
                    ldsm_x4t(v0h, vb + FVH);
                    ldsm_x4t(v1h, vb + FVH + 32);
                    mma_f16(o[4*dp + 0], ah, v0h[0], v0h[1]);
                    mma_f16(o[4*dp + 1], ah, v0h[2], v0h[3]);
                    mma_f16(o[4*dp + 2], ah, v1h[0], v1h[1]);
                    mma_f16(o[4*dp + 3], ah, v1h[2], v1h[3]);
                }
            }
        }
    }

    // ---- normalize + write fp16 hi to g_attn_h [B,S,H] ----
    const float inv0 = 1.f / l0, inv1 = 1.f / l1;
    const int b = bh >> 4, hd = bh & 15;
    const size_t ob0 = ((size_t)(b * SEQ + r0g)) * HID + hd * HDIM;
    const size_t ob1 = ob0 + (size_t)8 * HID;
#pragma unroll
    for (int nf = 0; nf < 16; ++nf) {
        const int col = nf * 8 + (lane & 3) * 2;
        *(uint32_t*)(g_attn_h + ob0 + col) = pack_h(o[nf][0] * inv0, o[nf][1] * inv0);
        *(uint32_t*)(g_attn_h + ob1 + col) = pack_h(o[nf][2] * inv1, o[nf][3] * inv1);
    }
}

// ---------------------------------------------------------------------------
extern "C" void kernel_launch(void* const* d_in, const int* in_sizes, int n_in,
                              void* d_out, int out_size)
{
    const float* hs    = (const float*)d_in[0];
    const float* W_in  = (const float*)d_in[1];
    const float* b_in  = (const float*)d_in[2];
    const float* W_out = (const float*)d_in[3];
    const float* b_out = (const float*)d_in[4];
    float* out = (float*)d_out;
    (void)in_sizes; (void)n_in; (void)out_size;

    // smem sizes
    constexpr int SM_QKV = 2 * (128 * ROWB + 2 * 192 * ROWB);   // 147456
    constexpr int SM_OUT = 2 * (128 * ROWB + 1 * 256 * ROWB);   // 110592

    cudaFuncSetAttribute((const void*)gemm_mma_kernel<0, 192, 2, HID>,
                         cudaFuncAttributeMaxDynamicSharedMemorySize, SM_QKV);
    cudaFuncSetAttribute((const void*)gemm_mma_kernel<1, 256, 1, HID>,
                         cudaFuncAttributeMaxDynamicSharedMemorySize, SM_OUT);
    cudaFuncSetAttribute(flash_mma_kernel,
                         cudaFuncAttributeMaxDynamicSharedMemorySize, FLASH_SMEM);

    __half *hs_h, *win_h, *win_l, *wout_h, *at_h;
    cudaGetSymbolAddress((void**)&hs_h,   g_hs_h);
    cudaGetSymbolAddress((void**)&win_h,  g_win_h);
    cudaGetSymbolAddress((void**)&win_l,  g_win_l);
    cudaGetSymbolAddress((void**)&wout_h, g_wout_h);
    cudaGetSymbolAddress((void**)&at_h,   g_attn_h);

    // 0) fp32 -> fp16 conversions
    cvt_h_kernel <<<2048, 256>>>(hs,    hs_h,          MROWS * HID / 4);
    cvt_hl_kernel<<<2048, 256>>>(W_in,  win_h, win_l,  NQKV * HID / 4);
    cvt_h_kernel <<<2048, 256>>>(W_out, wout_h,        HID * HID / 4);

    // 1) QKV projection (2-pass, N-tile 192 -> 1024 blocks, 98.8% wave eff)
    gemm_mma_kernel<0, 192, 2, HID>
        <<<dim3(NQKV / 192, MROWS / 128), 512, SM_QKV>>>(
        hs_h, win_h, win_l, b_in, nullptr);

    // 2) causal flash attention (QK 2-pass, PV 1-pass) -> g_attn_h
    flash_mma_kernel<<<dim3(SEQ / 128, BATCH * NHEADS), 256, FLASH_SMEM>>>();

    // 3) output projection (1-pass) -> d_out
    gemm_mma_kernel<1, 256, 1, HID>
        <<<dim3(HID / 256, MROWS / 128), 512, SM_OUT>>>(
        at_h, wout_h, nullptr, b_out, out);
}